// round 1
// baseline (speedup 1.0000x reference)
#include <cuda_runtime.h>
#include <cuda_bf16.h>
#include <stdint.h>

#define N_NODES 100000
#define IN_F 256
#define OUT_F 64

// Scratch for support = tanh(features @ weight)  [N, 64]
__device__ float g_support[(size_t)N_NODES * OUT_F];

// ---------------------------------------------------------------------------
// GEMM + tanh:  C[M,64] = act(A[M,256] @ W[256,64])
// Block tile 64x64, BK=32, 256 threads (16x16), 4x4 per thread.
// Packed f32x2 FMA: accumulators pair adjacent ROWS, B is duplicated in smem
// so both fma.rn.f32x2 operands load directly from shared with no packing MOVs.
// ---------------------------------------------------------------------------
#define BM 64
#define BN 64
#define BK 32
#define AS_STRIDE 68  // 64 + 4 pad (keeps 16B alignment, kills conflicts)

#define FMA_F32X2(d, a, b, c) \
    asm("fma.rn.f32x2 %0, %1, %2, %3;" : "=l"(d) : "l"(a), "l"(b), "l"(c))

// Wd layout: for col n (0..63), the duplicated pair {w,w} lives at
// k*128 + (n&3)*32 + (n>>2)*2   -> LDS.64 reads are bank-conflict-free.
__device__ __forceinline__ int wd_off(int n) {
    return ((n & 3) << 5) + ((n >> 2) << 1);
}

__global__ __launch_bounds__(256) void gemm_tanh_kernel(
    const float* __restrict__ A, const float* __restrict__ W,
    const int* __restrict__ active, float* __restrict__ C, int M)
{
    __shared__ float As[BK][AS_STRIDE];   // transposed: As[k][row]
    __shared__ float Wd[BK * 2 * BN];     // duplicated pairs, swizzled layout

    const int tid = threadIdx.x;
    const int tx = tid & 15;          // col group
    const int ty = tid >> 4;          // row group
    const int row0 = blockIdx.x * BM;

    unsigned long long acc[2][4];
    #pragma unroll
    for (int p = 0; p < 2; p++)
        #pragma unroll
        for (int j = 0; j < 4; j++) acc[p][j] = 0ull;

    for (int k0 = 0; k0 < IN_F; k0 += BK) {
        // --- load A tile (64 rows x 32 k), store transposed ---
        #pragma unroll
        for (int i = 0; i < 2; i++) {
            int idx = tid + i * 256;           // 0..511
            int r  = idx >> 3;                 // 0..63
            int kq = (idx & 7) << 2;           // 0,4,...,28
            int gr = row0 + r;
            float4 v = make_float4(0.f, 0.f, 0.f, 0.f);
            if (gr < M)
                v = *reinterpret_cast<const float4*>(&A[(size_t)gr * IN_F + k0 + kq]);
            As[kq + 0][r] = v.x;
            As[kq + 1][r] = v.y;
            As[kq + 2][r] = v.z;
            As[kq + 3][r] = v.w;
        }
        // --- load W tile (32 k x 64 n), duplicated pairs ---
        #pragma unroll
        for (int i = 0; i < 8; i++) {
            int idx = tid + i * 256;           // 0..2047
            int k = idx >> 6;                  // 0..31
            int n = idx & 63;                  // 0..63
            float w = W[(size_t)(k0 + k) * OUT_F + n];
            int o = k * 128 + wd_off(n);
            Wd[o] = w;
            Wd[o + 1] = w;
        }
        __syncthreads();

        #pragma unroll
        for (int k = 0; k < BK; k++) {
            // rows ty*4 .. ty*4+3 packed as two f32x2
            ulonglong2 aa = *reinterpret_cast<const ulonglong2*>(&As[k][ty << 2]);
            const float* wrow = &Wd[k * 128];
            #pragma unroll
            for (int j = 0; j < 4; j++) {
                unsigned long long bb =
                    *reinterpret_cast<const unsigned long long*>(
                        &wrow[(j << 5) + (tx << 1)]);
                FMA_F32X2(acc[0][j], aa.x, bb, acc[0][j]);
                FMA_F32X2(acc[1][j], aa.y, bb, acc[1][j]);
            }
        }
        __syncthreads();
    }

    const int act = *active;
    #pragma unroll
    for (int p = 0; p < 2; p++) {
        #pragma unroll
        for (int j = 0; j < 4; j++) {
            unsigned long long a2 = acc[p][j];
            float lo = __uint_as_float((unsigned)(a2 & 0xffffffffull));
            float hi = __uint_as_float((unsigned)(a2 >> 32));
            if (act) { lo = tanhf(lo); hi = tanhf(hi); }
            int rlo = row0 + (ty << 2) + p * 2;
            int n = (tx << 2) + j;
            if (rlo < M)     C[(size_t)rlo * OUT_F + n] = lo;
            if (rlo + 1 < M) C[(size_t)(rlo + 1) * OUT_F + n] = hi;
        }
    }
}

// ---------------------------------------------------------------------------
// SpMM: y[rows[e]] += vals[e] * x[cols[e]]   (rows sorted ascending)
// One warp per 32-edge chunk; each lane owns 2 of the 64 features.
// Register-accumulate runs of identical rows, flush via atomicAdd on change.
// ---------------------------------------------------------------------------
__global__ __launch_bounds__(256) void spmm_kernel(
    const int* __restrict__ rows, const int* __restrict__ cols,
    const float* __restrict__ vals, const float* __restrict__ x,
    float* __restrict__ y, int nE)
{
    const int warp = (blockIdx.x * blockDim.x + threadIdx.x) >> 5;
    const int lane = threadIdx.x & 31;
    const int e0 = warp * 32;
    if (e0 >= nE) return;
    const int n = min(32, nE - e0);

    int   r = (lane < n) ? rows[e0 + lane] : -1;
    int   c = (lane < n) ? cols[e0 + lane] : 0;
    float v = (lane < n) ? vals[e0 + lane] : 0.0f;

    const int f = lane << 1;   // feature pair owned by this lane
    float2 acc = make_float2(0.f, 0.f);
    int cur = __shfl_sync(0xffffffffu, r, 0);

    for (int i = 0; i < n; i++) {
        int   ri = __shfl_sync(0xffffffffu, r, i);
        int   ci = __shfl_sync(0xffffffffu, c, i);
        float vi = __shfl_sync(0xffffffffu, v, i);
        if (ri != cur) {
            float* dst = &y[(size_t)cur * OUT_F + f];
            atomicAdd(dst, acc.x);
            atomicAdd(dst + 1, acc.y);
            acc = make_float2(0.f, 0.f);
            cur = ri;
        }
        float2 xv = *reinterpret_cast<const float2*>(&x[(size_t)ci * OUT_F + f]);
        acc.x = fmaf(vi, xv.x, acc.x);
        acc.y = fmaf(vi, xv.y, acc.y);
    }
    float* dst = &y[(size_t)cur * OUT_F + f];
    atomicAdd(dst, acc.x);
    atomicAdd(dst + 1, acc.y);
}

// ---------------------------------------------------------------------------
extern "C" void kernel_launch(void* const* d_in, const int* in_sizes, int n_in,
                              void* d_out, int out_size)
{
    const float* features = (const float*)d_in[0];   // [N, 256]
    const float* weight   = (const float*)d_in[1];   // [256, 64]
    const int*   adj_rows = (const int*)d_in[2];     // [E] sorted
    const int*   adj_cols = (const int*)d_in[3];     // [E]
    const float* adj_vals = (const float*)d_in[4];   // [E]
    const int*   active   = (const int*)d_in[5];     // scalar

    const int M  = in_sizes[0] / IN_F;               // 100000
    const int nE = in_sizes[2];                      // 1600000

    float* out_first  = (float*)d_out;                          // output [N,64]
    float* out_second = (float*)d_out + (size_t)M * OUT_F;      // az     [N,64]

    float* support = nullptr;
    cudaGetSymbolAddress((void**)&support, g_support);

    // zero both output halves (atomics accumulate into them)
    cudaMemsetAsync(d_out, 0, (size_t)out_size * sizeof(float), 0);

    // 1) support = tanh(features @ weight)
    int gblocks = (M + BM - 1) / BM;
    gemm_tanh_kernel<<<gblocks, 256>>>(features, weight, active, support, M);

    // 2) output = adj @ support
    int warps = (nE + 31) / 32;
    int sblocks = (warps * 32 + 255) / 256;
    spmm_kernel<<<sblocks, 256>>>(adj_rows, adj_cols, adj_vals, support, out_first, nE);

    // 3) az = adj @ output
    spmm_kernel<<<sblocks, 256>>>(adj_rows, adj_cols, adj_vals, out_first, out_second, nE);
}

// round 2
// speedup vs baseline: 1.2726x; 1.2726x over previous
#include <cuda_runtime.h>
#include <cuda_bf16.h>
#include <stdint.h>

#define N_NODES 100000
#define IN_F 256
#define OUT_F 64

// Scratch for support = tanh(features @ weight)  [N, 64]
__device__ float g_support[(size_t)N_NODES * OUT_F];

// ---------------------------------------------------------------------------
// GEMM + tanh:  C[M,64] = act(A[M,256] @ W[256,64])
// Block tile 256x64, BK=16, 256 threads; per-thread 8x8 via f32x2 row pairs.
// As transposed [k][r] (stride 260 words: conflict-free reads, 16B aligned).
// Wd duplicated pairs [k][tx-group stride 20 words]: conflict-free LDS.128.
// ---------------------------------------------------------------------------
#define BM 256
#define BK 16
#define AS_STRIDE 260          // 256 + 4 pad words
#define WD_K_STRIDE 160        // 8 groups * 20 words
#define WD_TX_STRIDE 20        // 16 used + 4 pad words (80B)

#define FMA_F32X2(d, a, b, c) \
    asm("fma.rn.f32x2 %0, %1, %2, %3;" : "=l"(d) : "l"(a), "l"(b), "l"(c))

__device__ __forceinline__ float f2_lo(unsigned long long x) {
    return __uint_as_float((unsigned)(x & 0xffffffffull));
}
__device__ __forceinline__ float f2_hi(unsigned long long x) {
    return __uint_as_float((unsigned)(x >> 32));
}

__global__ __launch_bounds__(256, 2) void gemm_tanh_kernel(
    const float* __restrict__ A, const float* __restrict__ W,
    const int* __restrict__ active, float* __restrict__ C, int M)
{
    __shared__ float s_as[BK * AS_STRIDE];   // ~16.6KB
    __shared__ float s_wd[BK * WD_K_STRIDE]; // 10.2KB

    const int tid = threadIdx.x;
    const int tx = tid & 7;           // col group: cols 8tx..8tx+7
    const int ty = tid >> 3;          // row group: rows 8ty..8ty+7
    const int row0 = blockIdx.x * BM;

    unsigned long long acc[4][8];
    #pragma unroll
    for (int rp = 0; rp < 4; rp++)
        #pragma unroll
        for (int j = 0; j < 8; j++) acc[rp][j] = 0ull;

    for (int k0 = 0; k0 < IN_F; k0 += BK) {
        // --- A tile: 256 rows x 16 k, coalesced LDG.128, transposed stores ---
        #pragma unroll
        for (int i = 0; i < 4; i++) {
            int idx = tid + i * 256;          // 0..1023
            int r   = idx >> 2;               // 0..255
            int cq  = (idx & 3) << 2;         // 0,4,8,12
            int gr  = row0 + r;
            float4 v = make_float4(0.f, 0.f, 0.f, 0.f);
            if (gr < M)
                v = *reinterpret_cast<const float4*>(&A[(size_t)gr * IN_F + k0 + cq]);
            s_as[(cq + 0) * AS_STRIDE + r] = v.x;
            s_as[(cq + 1) * AS_STRIDE + r] = v.y;
            s_as[(cq + 2) * AS_STRIDE + r] = v.z;
            s_as[(cq + 3) * AS_STRIDE + r] = v.w;
        }
        // --- W tile: 16 k x 64 n, duplicated pairs, swizzled groups ---
        #pragma unroll
        for (int i = 0; i < 4; i++) {
            int idx = tid + i * 256;          // 0..1023
            int k = idx >> 6;                 // 0..15
            int n = idx & 63;                 // 0..63
            float w = W[(size_t)(k0 + k) * OUT_F + n];
            float2 p = make_float2(w, w);
            *reinterpret_cast<float2*>(
                &s_wd[k * WD_K_STRIDE + (n >> 3) * WD_TX_STRIDE + ((n & 7) << 1)]) = p;
        }
        __syncthreads();

        const float* as_base = &s_as[ty << 3];
        const float* wd_base = &s_wd[tx * WD_TX_STRIDE];
        #pragma unroll
        for (int k = 0; k < BK; k++) {
            // 8 rows -> 4 natural adjacent pairs (2x LDS.128)
            ulonglong2 a01 = *reinterpret_cast<const ulonglong2*>(&as_base[k * AS_STRIDE]);
            ulonglong2 a23 = *reinterpret_cast<const ulonglong2*>(&as_base[k * AS_STRIDE + 4]);
            // 8 cols duplicated -> 4x LDS.128 (2 dup-pairs each)
            const float* wr = &wd_base[k * WD_K_STRIDE];
            ulonglong2 b01 = *reinterpret_cast<const ulonglong2*>(&wr[0]);
            ulonglong2 b23 = *reinterpret_cast<const ulonglong2*>(&wr[4]);
            ulonglong2 b45 = *reinterpret_cast<const ulonglong2*>(&wr[8]);
            ulonglong2 b67 = *reinterpret_cast<const ulonglong2*>(&wr[12]);

            unsigned long long ap[4] = {a01.x, a01.y, a23.x, a23.y};
            unsigned long long bp[8] = {b01.x, b01.y, b23.x, b23.y,
                                        b45.x, b45.y, b67.x, b67.y};
            #pragma unroll
            for (int rp = 0; rp < 4; rp++) {
                #pragma unroll
                for (int j = 0; j < 8; j++) {
                    FMA_F32X2(acc[rp][j], ap[rp], bp[j], acc[rp][j]);
                }
            }
        }
        __syncthreads();
    }

    const int act = *active;
    const int ccol = tx << 3;
    #pragma unroll
    for (int rp = 0; rp < 4; rp++) {
        float vlo[8], vhi[8];
        #pragma unroll
        for (int j = 0; j < 8; j++) { vlo[j] = f2_lo(acc[rp][j]); vhi[j] = f2_hi(acc[rp][j]); }
        if (act) {
            #pragma unroll
            for (int j = 0; j < 8; j++) { vlo[j] = tanhf(vlo[j]); vhi[j] = tanhf(vhi[j]); }
        }
        int re = row0 + (ty << 3) + (rp << 1);
        if (re < M) {
            float4* dst = reinterpret_cast<float4*>(&C[(size_t)re * OUT_F + ccol]);
            dst[0] = make_float4(vlo[0], vlo[1], vlo[2], vlo[3]);
            dst[1] = make_float4(vlo[4], vlo[5], vlo[6], vlo[7]);
        }
        if (re + 1 < M) {
            float4* dst = reinterpret_cast<float4*>(&C[(size_t)(re + 1) * OUT_F + ccol]);
            dst[0] = make_float4(vhi[0], vhi[1], vhi[2], vhi[3]);
            dst[1] = make_float4(vhi[4], vhi[5], vhi[6], vhi[7]);
        }
    }
}

// ---------------------------------------------------------------------------
// SpMM: y[rows[e]] += vals[e] * x[cols[e]]   (rows sorted ascending)
// One warp per 32-edge chunk; each lane owns 2 of the 64 features.
// Register-accumulate runs of identical rows, flush via atomicAdd on change.
// ---------------------------------------------------------------------------
__global__ __launch_bounds__(256) void spmm_kernel(
    const int* __restrict__ rows, const int* __restrict__ cols,
    const float* __restrict__ vals, const float* __restrict__ x,
    float* __restrict__ y, int nE)
{
    const int warp = (blockIdx.x * blockDim.x + threadIdx.x) >> 5;
    const int lane = threadIdx.x & 31;
    const int e0 = warp * 32;
    if (e0 >= nE) return;
    const int n = min(32, nE - e0);

    int   r = (lane < n) ? rows[e0 + lane] : -1;
    int   c = (lane < n) ? cols[e0 + lane] : 0;
    float v = (lane < n) ? vals[e0 + lane] : 0.0f;

    const int f = lane << 1;   // feature pair owned by this lane
    float2 acc = make_float2(0.f, 0.f);
    int cur = __shfl_sync(0xffffffffu, r, 0);

    for (int i = 0; i < n; i++) {
        int   ri = __shfl_sync(0xffffffffu, r, i);
        int   ci = __shfl_sync(0xffffffffu, c, i);
        float vi = __shfl_sync(0xffffffffu, v, i);
        if (ri != cur) {
            float* dst = &y[(size_t)cur * OUT_F + f];
            atomicAdd(dst, acc.x);
            atomicAdd(dst + 1, acc.y);
            acc = make_float2(0.f, 0.f);
            cur = ri;
        }
        float2 xv = *reinterpret_cast<const float2*>(&x[(size_t)ci * OUT_F + f]);
        acc.x = fmaf(vi, xv.x, acc.x);
        acc.y = fmaf(vi, xv.y, acc.y);
    }
    float* dst = &y[(size_t)cur * OUT_F + f];
    atomicAdd(dst, acc.x);
    atomicAdd(dst + 1, acc.y);
}

// ---------------------------------------------------------------------------
extern "C" void kernel_launch(void* const* d_in, const int* in_sizes, int n_in,
                              void* d_out, int out_size)
{
    const float* features = (const float*)d_in[0];   // [N, 256]
    const float* weight   = (const float*)d_in[1];   // [256, 64]
    const int*   adj_rows = (const int*)d_in[2];     // [E] sorted
    const int*   adj_cols = (const int*)d_in[3];     // [E]
    const float* adj_vals = (const float*)d_in[4];   // [E]
    const int*   active   = (const int*)d_in[5];     // scalar

    const int M  = in_sizes[0] / IN_F;               // 100000
    const int nE = in_sizes[2];                      // 1600000

    float* out_first  = (float*)d_out;                          // output [N,64]
    float* out_second = (float*)d_out + (size_t)M * OUT_F;      // az     [N,64]

    float* support = nullptr;
    cudaGetSymbolAddress((void**)&support, g_support);

    // zero both output halves (atomics accumulate into them)
    cudaMemsetAsync(d_out, 0, (size_t)out_size * sizeof(float), 0);

    // 1) support = tanh(features @ weight)
    int gblocks = (M + BM - 1) / BM;
    gemm_tanh_kernel<<<gblocks, 256>>>(features, weight, active, support, M);

    // 2) output = adj @ support
    int warps = (nE + 31) / 32;
    int sblocks = (warps * 32 + 255) / 256;
    spmm_kernel<<<sblocks, 256>>>(adj_rows, adj_cols, adj_vals, support, out_first, nE);

    // 3) az = adj @ output
    spmm_kernel<<<sblocks, 256>>>(adj_rows, adj_cols, adj_vals, out_first, out_second, nE);
}